// round 8
// baseline (speedup 1.0000x reference)
#include <cuda_runtime.h>
#include <cuda_bf16.h>
#include <cstdint>
#include <cstddef>

// Problem constants
#define T_  2048
#define B_  256
#define I_  64
#define H_  128
#define G_  512          // 4*H gate rows
#define NH_ 512
#define O_  64
#define TB_ (T_ * B_)    // 524288

// Scan weight split: kc chunks 0..KC_SM-1 in shared memory, KC_SM..31 in registers
#define KC_SM 20
#define KC_RG (32 - KC_SM)   // 12 chunks -> 48 registers/thread

// ---------------------------------------------------------------------------
// Scratch: __device__ globals (allocation-free rule).
//   g_xg : [TB,512] gate preactivations (1 GiB); reused as MLP hidden buffer.
//   g_hs : [TB,128] all hidden states (256 MiB).
//   g_wt4: W_hh in k-chunked float4 layout: g_wt4[kc*512+g] = W_hh[g][4kc..4kc+3]
// ---------------------------------------------------------------------------
__device__ float  g_xg[(size_t)TB_ * G_];
__device__ float  g_hs[(size_t)TB_ * H_];
__device__ float4 g_wt4[32 * G_];

// ---------------------------------------------------------------------------
// K0: transpose W_hh [512,128] row-major -> g_wt4
// ---------------------------------------------------------------------------
__global__ void k_twhh(const float* __restrict__ Whh) {
    int idx = blockIdx.x * 256 + threadIdx.x;      // 65536 elements
    int g = idx >> 7;          // 0..511
    int k = idx & 127;         // 0..127
    ((float*)g_wt4)[((k >> 2) * G_ + g) * 4 + (k & 3)] = Whh[idx];
}

// ---------------------------------------------------------------------------
// Generic tiled GEMM: C[m][n] = sum_k A[m*K+k] * W[n*K+k] + bias[n] (+bias2[n])
// BM=BN=64, BK=16, 256 threads, 4x4 microtile. K,M,N multiples of 16/64.
// ---------------------------------------------------------------------------
template <bool RELU>
__global__ __launch_bounds__(256) void k_gemm(
    const float* __restrict__ A, const float* __restrict__ W,
    const float* __restrict__ bias, const float* __restrict__ bias2,
    float* __restrict__ C, int M, int N, int K)
{
    __shared__ float As[16][68];   // pad 68: float4-aligned rows, conflict-free staging
    __shared__ float Ws[16][68];

    const int tid = threadIdx.x;
    const int tx = tid & 15;       // n microtile
    const int ty = tid >> 4;       // m microtile
    const int m0 = blockIdx.x * 64;
    const int n0 = blockIdx.y * 64;

    const int lrow = tid >> 2;         // 0..63
    const int lkq  = (tid & 3) * 4;    // 0,4,8,12

    const float* Aptr = A + (size_t)(m0 + lrow) * K + lkq;
    const float* Wptr = W + (size_t)(n0 + lrow) * K + lkq;

    float acc[4][4];
#pragma unroll
    for (int i = 0; i < 4; i++)
#pragma unroll
        for (int j = 0; j < 4; j++) acc[i][j] = 0.f;

    for (int kk = 0; kk < K; kk += 16) {
        float4 av = *(const float4*)(Aptr + kk);
        float4 wv = *(const float4*)(Wptr + kk);
        As[lkq + 0][lrow] = av.x; As[lkq + 1][lrow] = av.y;
        As[lkq + 2][lrow] = av.z; As[lkq + 3][lrow] = av.w;
        Ws[lkq + 0][lrow] = wv.x; Ws[lkq + 1][lrow] = wv.y;
        Ws[lkq + 2][lrow] = wv.z; Ws[lkq + 3][lrow] = wv.w;
        __syncthreads();

#pragma unroll
        for (int k = 0; k < 16; k++) {
            float4 a = *(const float4*)&As[k][ty * 4];
            float4 w = *(const float4*)&Ws[k][tx * 4];
            acc[0][0] = fmaf(a.x, w.x, acc[0][0]);
            acc[0][1] = fmaf(a.x, w.y, acc[0][1]);
            acc[0][2] = fmaf(a.x, w.z, acc[0][2]);
            acc[0][3] = fmaf(a.x, w.w, acc[0][3]);
            acc[1][0] = fmaf(a.y, w.x, acc[1][0]);
            acc[1][1] = fmaf(a.y, w.y, acc[1][1]);
            acc[1][2] = fmaf(a.y, w.z, acc[1][2]);
            acc[1][3] = fmaf(a.y, w.w, acc[1][3]);
            acc[2][0] = fmaf(a.z, w.x, acc[2][0]);
            acc[2][1] = fmaf(a.z, w.y, acc[2][1]);
            acc[2][2] = fmaf(a.z, w.z, acc[2][2]);
            acc[2][3] = fmaf(a.z, w.w, acc[2][3]);
            acc[3][0] = fmaf(a.w, w.x, acc[3][0]);
            acc[3][1] = fmaf(a.w, w.y, acc[3][1]);
            acc[3][2] = fmaf(a.w, w.z, acc[3][2]);
            acc[3][3] = fmaf(a.w, w.w, acc[3][3]);
        }
        __syncthreads();
    }

    float b[4];
#pragma unroll
    for (int j = 0; j < 4; j++) {
        b[j] = bias[n0 + tx * 4 + j];
        if (bias2) b[j] += bias2[n0 + tx * 4 + j];
    }
#pragma unroll
    for (int i = 0; i < 4; i++) {
        float4 o;
        o.x = acc[i][0] + b[0];
        o.y = acc[i][1] + b[1];
        o.z = acc[i][2] + b[2];
        o.w = acc[i][3] + b[3];
        if (RELU) {
            o.x = fmaxf(o.x, 0.f); o.y = fmaxf(o.y, 0.f);
            o.z = fmaxf(o.z, 0.f); o.w = fmaxf(o.w, 0.f);
        }
        *(float4*)&C[(size_t)(m0 + ty * 4 + i) * N + n0 + tx * 4] = o;
    }
}

// ---------------------------------------------------------------------------
// K2: LSTM scan. 128 CTAs (2 batch rows each), 512 threads (1 per gate row).
// ---------------------------------------------------------------------------
__device__ __forceinline__ float sigf(float x) {
    return __fdividef(1.f, 1.f + __expf(-x));
}
__device__ __forceinline__ float tanhf_fast(float x) {
    return __fdividef(2.f, 1.f + __expf(-2.f * x)) - 1.f;
}

#define SCAN_SMEM ((KC_SM * G_ + 64) * 16 + 2 * G_ * 4)

__global__ __launch_bounds__(512, 1) void k_scan(float* __restrict__ hT_out,
                                                 float* __restrict__ cT_out)
{
    extern __shared__ float4 sm4[];
    float4* W4s = sm4;                         // [KC_SM * 512]
    float4* h4  = sm4 + KC_SM * G_;            // [2][32]  (h as float4)
    float*  gsm = (float*)(sm4 + KC_SM * G_ + 64);  // [2][512] gates

    const int g  = threadIdx.x;                // gate row 0..511
    const int b0 = blockIdx.x * 2;
    const int b1 = b0 + 1;

    // Load smem-resident weight chunks
    for (int idx = g; idx < KC_SM * G_; idx += 512) W4s[idx] = g_wt4[idx];
    // Register-resident weight chunks (constant across all 2048 steps)
    float4 wg[KC_RG];
#pragma unroll
    for (int q = 0; q < KC_RG; q++) wg[q] = g_wt4[(KC_SM + q) * G_ + g];

    // h = 0
    if (g < 64) h4[g] = make_float4(0.f, 0.f, 0.f, 0.f);
    float c0 = 0.f, c1 = 0.f;

    // prefetch xg for t=0
    float xg0 = g_xg[(size_t)(0 * B_ + b0) * G_ + g];
    float xg1 = g_xg[(size_t)(0 * B_ + b1) * G_ + g];
    __syncthreads();

    for (int t = 0; t < T_; t++) {
        // prefetch next step's xg (latency hidden by gate compute)
        int tn = (t < T_ - 1) ? t + 1 : t;
        float nxt0 = g_xg[(size_t)(tn * B_ + b0) * G_ + g];
        float nxt1 = g_xg[(size_t)(tn * B_ + b1) * G_ + g];

        float acc0 = xg0, acc1 = xg1;
#pragma unroll
        for (int kc = 0; kc < 32; kc++) {
            float4 w  = (kc < KC_SM) ? W4s[kc * G_ + g] : wg[kc - KC_SM];
            float4 ha = h4[kc];
            float4 hb = h4[32 + kc];
            acc0 = fmaf(w.x, ha.x, acc0);
            acc0 = fmaf(w.y, ha.y, acc0);
            acc0 = fmaf(w.z, ha.z, acc0);
            acc0 = fmaf(w.w, ha.w, acc0);
            acc1 = fmaf(w.x, hb.x, acc1);
            acc1 = fmaf(w.y, hb.y, acc1);
            acc1 = fmaf(w.z, hb.z, acc1);
            acc1 = fmaf(w.w, hb.w, acc1);
        }
        gsm[g]      = acc0;
        gsm[G_ + g] = acc1;
        __syncthreads();

        if (g < H_) {
            // batch row 0
            float ig = sigf(gsm[g]);
            float fg = sigf(gsm[H_ + g]);
            float gg = tanhf_fast(gsm[2 * H_ + g]);
            float og = sigf(gsm[3 * H_ + g]);
            c0 = fmaf(fg, c0, ig * gg);
            float h0 = og * tanhf_fast(c0);
            ((float*)h4)[g] = h0;
            g_hs[(size_t)(t * B_ + b0) * H_ + g] = h0;
            // batch row 1
            ig = sigf(gsm[G_ + g]);
            fg = sigf(gsm[G_ + H_ + g]);
            gg = tanhf_fast(gsm[G_ + 2 * H_ + g]);
            og = sigf(gsm[G_ + 3 * H_ + g]);
            c1 = fmaf(fg, c1, ig * gg);
            float h1 = og * tanhf_fast(c1);
            ((float*)(h4 + 32))[g] = h1;
            g_hs[(size_t)(t * B_ + b1) * H_ + g] = h1;
        }
        __syncthreads();
        xg0 = nxt0; xg1 = nxt1;
    }

    // final (h_n, c_n) into output tail
    if (g < H_) {
        hT_out[b0 * H_ + g] = ((float*)h4)[g];
        hT_out[b1 * H_ + g] = ((float*)(h4 + 32))[g];
        cT_out[b0 * H_ + g] = c0;
        cT_out[b1 * H_ + g] = c1;
    }
}

// ---------------------------------------------------------------------------
// Launcher
// ---------------------------------------------------------------------------
extern "C" void kernel_launch(void* const* d_in, const int* in_sizes, int n_in,
                              void* d_out, int out_size)
{
    const float* x    = (const float*)d_in[0];  // [T,B,I]
    const float* W_ih = (const float*)d_in[1];  // [512,64]
    const float* W_hh = (const float*)d_in[2];  // [512,128]
    const float* b_ih = (const float*)d_in[3];  // [512]
    const float* b_hh = (const float*)d_in[4];  // [512]
    const float* W1   = (const float*)d_in[5];  // [512,128]
    const float* b1   = (const float*)d_in[6];  // [512]
    const float* W2   = (const float*)d_in[7];  // [64,512]
    const float* b2   = (const float*)d_in[8];  // [64]

    float* out = (float*)d_out;                      // [T,B,64]
    float* hT  = out + (size_t)TB_ * O_;             // [1,256,128]
    float* cT  = hT + (size_t)B_ * H_;               // [1,256,128]

    float* xg; float* hs;
    cudaGetSymbolAddress((void**)&xg, g_xg);
    cudaGetSymbolAddress((void**)&hs, g_hs);

    static_assert(SCAN_SMEM <= 232448, "scan smem over limit");
    cudaFuncSetAttribute(k_scan, cudaFuncAttributeMaxDynamicSharedMemorySize,
                         SCAN_SMEM);

    // K0: weight transpose for the scan
    k_twhh<<<(G_ * H_) / 256, 256>>>(W_hh);

    // K1: xg = x @ W_ih^T + (b_ih + b_hh)   [TB,512]
    k_gemm<false><<<dim3(TB_ / 64, G_ / 64), 256>>>(
        x, W_ih, b_ih, b_hh, xg, TB_, G_, I_);

    // K2: sequential LSTM scan -> g_hs, hT, cT
    k_scan<<<B_ / 2, 512, SCAN_SMEM>>>(hT, cT);

    // K3: hidden = relu(hs @ W1^T + b1)   [TB,512]  (reuses g_xg)
    k_gemm<true><<<dim3(TB_ / 64, NH_ / 64), 256>>>(
        hs, W1, b1, nullptr, xg, TB_, NH_, H_);

    // K4: out = hidden @ W2^T + b2   [TB,64]
    k_gemm<false><<<dim3(TB_ / 64, O_ / 64), 256>>>(
        xg, W2, b2, nullptr, out, TB_, O_, NH_);
}

// round 9
// speedup vs baseline: 1.2375x; 1.2375x over previous
#include <cuda_runtime.h>
#include <cuda_bf16.h>
#include <cstdint>
#include <cstddef>

// Problem constants
#define T_  2048
#define B_  256
#define I_  64
#define H_  128
#define G_  512          // 4*H gate rows
#define NH_ 512
#define O_  64
#define TB_ (T_ * B_)    // 524288

// ---------------------------------------------------------------------------
// f32x2 packed-math helpers (ptxas never emits FFMA2 from C++; PTX only)
// ---------------------------------------------------------------------------
__device__ __forceinline__ void fma2(unsigned long long& d,
                                     unsigned long long a,
                                     unsigned long long b) {
    asm("fma.rn.f32x2 %0, %1, %2, %0;" : "+l"(d) : "l"(a), "l"(b));
}
__device__ __forceinline__ unsigned long long dup2(float x) {
    unsigned long long r;
    asm("mov.b64 %0, {%1, %1};" : "=l"(r) : "f"(x));
    return r;
}
__device__ __forceinline__ void unpack2(unsigned long long v, float& lo, float& hi) {
    asm("mov.b64 {%0, %1}, %2;" : "=f"(lo), "=f"(hi) : "l"(v));
}
__device__ __forceinline__ float hadd2(unsigned long long v) {
    float lo, hi; unpack2(v, lo, hi); return lo + hi;
}

// ---------------------------------------------------------------------------
// Scratch: __device__ globals (allocation-free rule).
// ---------------------------------------------------------------------------
__device__ float  g_xg[(size_t)TB_ * G_];   // gate preacts; reused as MLP hidden
__device__ float  g_hs[(size_t)TB_ * H_];   // all hidden states
__device__ float4 g_wt4[32 * G_];           // W_hh k-chunked: [kc*512+g] = W[g][4kc..]

// ---------------------------------------------------------------------------
// K0: transpose W_hh [512,128] row-major -> g_wt4
// ---------------------------------------------------------------------------
__global__ void k_twhh(const float* __restrict__ Whh) {
    int idx = blockIdx.x * 256 + threadIdx.x;      // 65536 elements
    int g = idx >> 7;
    int k = idx & 127;
    ((float*)g_wt4)[((k >> 2) * G_ + g) * 4 + (k & 3)] = Whh[idx];
}

// ---------------------------------------------------------------------------
// GEMM v2: C[m][n] = sum_k A[m*K+k]*W[n*K+k] + bias[n] (+bias2[n]), opt. relu.
// 256 threads, BK=16, TMxTN microtile, m-packed FFMA2 (acc pair = 2 rows).
// Requires M % BM == 0, N % BN == 0, K % 16 == 0, (BM/TM)*(BN/TN) == 256.
// ---------------------------------------------------------------------------
template <int BM, int BN, int TM, int TN, bool RELU>
__global__ __launch_bounds__(256) void k_gemm2(
    const float* __restrict__ A, const float* __restrict__ W,
    const float* __restrict__ bias, const float* __restrict__ bias2,
    float* __restrict__ C, int M, int N, int K)
{
    constexpr int BK = 16;
    constexpr int NX = BN / TN;          // threads along n
    __shared__ float As[BK][BM + 4];     // transposed: As[k][m]
    __shared__ float Ws[BK][BN + 4];     // transposed: Ws[k][n]

    const int tid = threadIdx.x;
    const int tx = tid % NX;
    const int ty = tid / NX;
    const int m0 = blockIdx.x * BM;
    const int n0 = blockIdx.y * BN;

    const int lkq  = (tid & 3) * 4;      // k offset for staging float4
    const int lrow = tid >> 2;           // 0..63

    unsigned long long acc[TM / 2][TN];
#pragma unroll
    for (int i = 0; i < TM / 2; i++)
#pragma unroll
        for (int j = 0; j < TN; j++) acc[i][j] = 0ull;

    for (int kk = 0; kk < K; kk += BK) {
        // stage A (BM rows) and W (BN rows), transposed into smem
#pragma unroll
        for (int r = 0; r < BM / 64; r++) {
            float4 v = *(const float4*)&A[(size_t)(m0 + lrow + r * 64) * K + kk + lkq];
            As[lkq + 0][lrow + r * 64] = v.x;
            As[lkq + 1][lrow + r * 64] = v.y;
            As[lkq + 2][lrow + r * 64] = v.z;
            As[lkq + 3][lrow + r * 64] = v.w;
        }
#pragma unroll
        for (int r = 0; r < BN / 64; r++) {
            float4 v = *(const float4*)&W[(size_t)(n0 + lrow + r * 64) * K + kk + lkq];
            Ws[lkq + 0][lrow + r * 64] = v.x;
            Ws[lkq + 1][lrow + r * 64] = v.y;
            Ws[lkq + 2][lrow + r * 64] = v.z;
            Ws[lkq + 3][lrow + r * 64] = v.w;
        }
        __syncthreads();

#pragma unroll
        for (int k = 0; k < BK; k++) {
            // a: TM consecutive m values as TM/2 packed pairs (no movs)
            unsigned long long ap[TM / 2];
#pragma unroll
            for (int q = 0; q < TM / 4; q++) {
                ulonglong2 av = *(const ulonglong2*)&As[k][ty * TM + q * 4];
                ap[q * 2 + 0] = av.x;
                ap[q * 2 + 1] = av.y;
            }
            // w: TN scalars, duplicated into pairs
            unsigned long long wd[TN];
#pragma unroll
            for (int q = 0; q < TN / 4; q++) {
                float4 wv = *(const float4*)&Ws[k][tx * TN + q * 4];
                wd[q * 4 + 0] = dup2(wv.x);
                wd[q * 4 + 1] = dup2(wv.y);
                wd[q * 4 + 2] = dup2(wv.z);
                wd[q * 4 + 3] = dup2(wv.w);
            }
#pragma unroll
            for (int i = 0; i < TM / 2; i++)
#pragma unroll
                for (int j = 0; j < TN; j++)
                    fma2(acc[i][j], ap[i], wd[j]);
        }
        __syncthreads();
    }

    float b[TN];
#pragma unroll
    for (int j = 0; j < TN; j++) {
        b[j] = bias[n0 + tx * TN + j];
        if (bias2) b[j] += bias2[n0 + tx * TN + j];
    }

#pragma unroll
    for (int i = 0; i < TM / 2; i++) {
        float lo[TN], hi[TN];
#pragma unroll
        for (int j = 0; j < TN; j++) {
            unpack2(acc[i][j], lo[j], hi[j]);
            lo[j] += b[j]; hi[j] += b[j];
            if (RELU) { lo[j] = fmaxf(lo[j], 0.f); hi[j] = fmaxf(hi[j], 0.f); }
        }
        size_t r0 = (size_t)(m0 + ty * TM + 2 * i) * N + n0 + tx * TN;
        size_t r1 = r0 + N;
#pragma unroll
        for (int q = 0; q < TN / 4; q++) {
            *(float4*)&C[r0 + q * 4] = make_float4(lo[q*4], lo[q*4+1], lo[q*4+2], lo[q*4+3]);
            *(float4*)&C[r1 + q * 4] = make_float4(hi[q*4], hi[q*4+1], hi[q*4+2], hi[q*4+3]);
        }
    }
}

// ---------------------------------------------------------------------------
// K2 v2: LSTM scan. 128 CTAs (2 batch rows), 256 threads (2 gate rows each),
// k-packed FFMA2 (no dup movs in hot loop). 20/32 weight chunks in registers.
// ---------------------------------------------------------------------------
__device__ __forceinline__ float sigf(float x) {
    return __fdividef(1.f, 1.f + __expf(-x));
}
__device__ __forceinline__ float tanhf_fast(float x) {
    return __fdividef(2.f, 1.f + __expf(-2.f * x)) - 1.f;
}

#define SC_KCSM 12
#define SC_KCRG (32 - SC_KCSM)     // 20 chunks/gate in regs
#define HS_PAD  (H_ + 4)
// floats: W (12*512*4) + hsm (2*HS_PAD) + gsm (2*512)
#define SCAN_SMEM ((SC_KCSM * G_ * 4 + 2 * HS_PAD + 2 * G_) * 4)

__global__ __launch_bounds__(256, 1) void k_scan2(float* __restrict__ hT_out,
                                                  float* __restrict__ cT_out)
{
    extern __shared__ float smf[];
    float4* W4s = (float4*)smf;                         // [SC_KCSM*512]
    float*  hsm = smf + SC_KCSM * G_ * 4;               // [2][HS_PAD]
    float*  gsm = hsm + 2 * HS_PAD;                     // [2][512]

    const int t  = threadIdx.x;         // 0..255
    const int g0 = t;                   // gate rows owned
    const int g1 = t + 256;
    const int b0 = blockIdx.x * 2;

    // smem-resident weight chunks
    for (int idx = t; idx < SC_KCSM * G_; idx += 256) W4s[idx] = g_wt4[idx];
    // register-resident weight chunks (packed pairs, constant across steps)
    ulonglong2 wr0[SC_KCRG], wr1[SC_KCRG];
#pragma unroll
    for (int q = 0; q < SC_KCRG; q++) {
        wr0[q] = *(const ulonglong2*)&g_wt4[(SC_KCSM + q) * G_ + g0];
        wr1[q] = *(const ulonglong2*)&g_wt4[(SC_KCSM + q) * G_ + g1];
    }

    // h = 0; epilogue thread state: (b, j) = (t>>7, t&127)
    if (t < H_) { hsm[t] = 0.f; hsm[HS_PAD + t] = 0.f; }
    const int eb = t >> 7;
    const int ej = t & 127;
    float cst = 0.f;

    // xg prefetch for t=0 (4 streams: 2 gates x 2 batch)
    const float* xgp = g_xg + (size_t)b0 * G_;
    float x00 = xgp[g0],      x01 = xgp[G_ + g0];
    float x10 = xgp[g1],      x11 = xgp[G_ + g1];
    __syncthreads();

    for (int ts = 0; ts < T_; ts++) {
        int tn = (ts < T_ - 1) ? ts + 1 : ts;
        const float* xgn = g_xg + ((size_t)tn * B_ + b0) * G_;
        float n00 = xgn[g0], n01 = xgn[G_ + g0];
        float n10 = xgn[g1], n11 = xgn[G_ + g1];

        unsigned long long a00 = 0ull, a01 = 0ull, a10 = 0ull, a11 = 0ull;
#pragma unroll
        for (int kc = 0; kc < 32; kc++) {
            ulonglong2 w0 = (kc < SC_KCSM)
                ? *(const ulonglong2*)&W4s[kc * G_ + g0] : wr0[kc - SC_KCSM];
            ulonglong2 w1 = (kc < SC_KCSM)
                ? *(const ulonglong2*)&W4s[kc * G_ + g1] : wr1[kc - SC_KCSM];
            ulonglong2 h0 = *(const ulonglong2*)&hsm[kc * 4];
            ulonglong2 h1 = *(const ulonglong2*)&hsm[HS_PAD + kc * 4];
            fma2(a00, w0.x, h0.x); fma2(a00, w0.y, h0.y);
            fma2(a01, w0.x, h1.x); fma2(a01, w0.y, h1.y);
            fma2(a10, w1.x, h0.x); fma2(a10, w1.y, h0.y);
            fma2(a11, w1.x, h1.x); fma2(a11, w1.y, h1.y);
        }
        gsm[g0]       = hadd2(a00) + x00;
        gsm[G_ + g0]  = hadd2(a01) + x01;
        gsm[g1]       = hadd2(a10) + x10;
        gsm[G_ + g1]  = hadd2(a11) + x11;
        __syncthreads();

        // epilogue: all 256 threads, one (batch,unit) pair each
        {
            const float* gb = gsm + eb * G_;
            float ig = sigf(gb[ej]);
            float fg = sigf(gb[H_ + ej]);
            float gg = tanhf_fast(gb[2 * H_ + ej]);
            float og = sigf(gb[3 * H_ + ej]);
            cst = fmaf(fg, cst, ig * gg);
            float hv = og * tanhf_fast(cst);
            hsm[eb * HS_PAD + ej] = hv;
            g_hs[(size_t)(ts * B_ + b0 + eb) * H_ + ej] = hv;
        }
        __syncthreads();
        x00 = n00; x01 = n01; x10 = n10; x11 = n11;
    }

    hT_out[(b0 + eb) * H_ + ej] = hsm[eb * HS_PAD + ej];
    cT_out[(b0 + eb) * H_ + ej] = cst;
}

// ---------------------------------------------------------------------------
// Launcher
// ---------------------------------------------------------------------------
extern "C" void kernel_launch(void* const* d_in, const int* in_sizes, int n_in,
                              void* d_out, int out_size)
{
    const float* x    = (const float*)d_in[0];  // [T,B,I]
    const float* W_ih = (const float*)d_in[1];  // [512,64]
    const float* W_hh = (const float*)d_in[2];  // [512,128]
    const float* b_ih = (const float*)d_in[3];  // [512]
    const float* b_hh = (const float*)d_in[4];  // [512]
    const float* W1   = (const float*)d_in[5];  // [512,128]
    const float* b1   = (const float*)d_in[6];  // [512]
    const float* W2   = (const float*)d_in[7];  // [64,512]
    const float* b2   = (const float*)d_in[8];  // [64]

    float* out = (float*)d_out;                      // [T,B,64]
    float* hT  = out + (size_t)TB_ * O_;             // [1,256,128]
    float* cT  = hT + (size_t)B_ * H_;               // [1,256,128]

    float* xg; float* hs;
    cudaGetSymbolAddress((void**)&xg, g_xg);
    cudaGetSymbolAddress((void**)&hs, g_hs);

    static_assert(SCAN_SMEM <= 232448, "scan smem over limit");
    cudaFuncSetAttribute(k_scan2, cudaFuncAttributeMaxDynamicSharedMemorySize,
                         SCAN_SMEM);

    // K0: weight transpose for the scan
    k_twhh<<<(G_ * H_) / 256, 256>>>(W_hh);

    // K1: xg = x @ W_ih^T + (b_ih + b_hh)   [TB,512]
    k_gemm2<128, 128, 8, 8, false><<<dim3(TB_ / 128, G_ / 128), 256>>>(
        x, W_ih, b_ih, b_hh, xg, TB_, G_, I_);

    // K2: sequential LSTM scan -> g_hs, hT, cT
    k_scan2<<<B_ / 2, 256, SCAN_SMEM>>>(hT, cT);

    // K3: hidden = relu(hs @ W1^T + b1)   [TB,512]  (reuses g_xg)
    k_gemm2<128, 128, 8, 8, true><<<dim3(TB_ / 128, NH_ / 128), 256>>>(
        hs, W1, b1, nullptr, xg, TB_, NH_, H_);

    // K4: out = hidden @ W2^T + b2   [TB,64]
    k_gemm2<128, 64, 8, 4, false><<<dim3(TB_ / 128, O_ / 64), 256>>>(
        xg, W2, b2, nullptr, out, TB_, O_, NH_);
}

// round 10
// speedup vs baseline: 1.2754x; 1.0306x over previous
#include <cuda_runtime.h>
#include <cuda_bf16.h>
#include <cstdint>
#include <cstddef>

// Problem constants
#define T_  2048
#define B_  256
#define I_  64
#define H_  128
#define G_  512          // 4*H gate rows
#define NH_ 512
#define O_  64
#define TB_ (T_ * B_)    // 524288

// ---------------------------------------------------------------------------
// f32x2 packed-math helpers (ptxas never emits FFMA2 from C++; PTX only)
// ---------------------------------------------------------------------------
__device__ __forceinline__ void fma2(unsigned long long& d,
                                     unsigned long long a,
                                     unsigned long long b) {
    asm("fma.rn.f32x2 %0, %1, %2, %0;" : "+l"(d) : "l"(a), "l"(b));
}
__device__ __forceinline__ unsigned long long dup2(float x) {
    unsigned long long r;
    asm("mov.b64 %0, {%1, %1};" : "=l"(r) : "f"(x));
    return r;
}
__device__ __forceinline__ void unpack2(unsigned long long v, float& lo, float& hi) {
    asm("mov.b64 {%0, %1}, %2;" : "=f"(lo), "=f"(hi) : "l"(v));
}
__device__ __forceinline__ float hadd2(unsigned long long v) {
    float lo, hi; unpack2(v, lo, hi); return lo + hi;
}

// ---------------------------------------------------------------------------
// Scratch: __device__ globals (allocation-free rule).
// ---------------------------------------------------------------------------
__device__ float  g_xg[(size_t)TB_ * G_];   // gate preacts; reused as MLP hidden
__device__ float  g_hs[(size_t)TB_ * H_];   // all hidden states
__device__ float4 g_wt4[32 * G_];           // W_hh k-chunked: [kc*512+g] = W[g][4kc..]

// ---------------------------------------------------------------------------
// K0: transpose W_hh [512,128] row-major -> g_wt4
// ---------------------------------------------------------------------------
__global__ void k_twhh(const float* __restrict__ Whh) {
    int idx = blockIdx.x * 256 + threadIdx.x;      // 65536 elements
    int g = idx >> 7;
    int k = idx & 127;
    ((float*)g_wt4)[((k >> 2) * G_ + g) * 4 + (k & 3)] = Whh[idx];
}

// ---------------------------------------------------------------------------
// GEMM v3: C[m][n] = sum_k A[m*K+k]*W[n*K+k] + bias[n] (+bias2[n]), opt relu.
// BM=128, BN=64, BK=32, 256 threads, 8x4 microtile (m-packed FFMA2),
// double-buffered smem (1 barrier per k-tile), global->reg prefetch.
// Requires M%128==0, N%64==0, K%32==0.
// ---------------------------------------------------------------------------
template <bool RELU>
__global__ __launch_bounds__(256, 3) void k_gemm3(
    const float* __restrict__ A, const float* __restrict__ W,
    const float* __restrict__ bias, const float* __restrict__ bias2,
    float* __restrict__ C, int M, int N, int K)
{
    constexpr int BM = 128, BN = 64, BK = 32, TM = 8, TN = 4, NX = BN / TN;
    __shared__ float As[2][BK][BM + 4];   // transposed: As[buf][k][m]
    __shared__ float Ws[2][BK][BN + 4];

    const int tid = threadIdx.x;
    const int tx = tid % NX;             // 0..15
    const int ty = tid / NX;             // 0..15
    const int m0 = blockIdx.x * BM;
    const int n0 = blockIdx.y * BN;

    const int lkq  = (tid & 7) * 4;      // 0,4,...,28
    const int lrow = tid >> 3;           // 0..31

    const float* Ap = A + (size_t)(m0 + lrow) * K + lkq;
    const float* Wp = W + (size_t)(n0 + lrow) * K + lkq;

    unsigned long long acc[TM / 2][TN];
#pragma unroll
    for (int i = 0; i < TM / 2; i++)
#pragma unroll
        for (int j = 0; j < TN; j++) acc[i][j] = 0ull;

    float4 pa[4], pw[2];

    // prologue: load + stage tile 0
#pragma unroll
    for (int r = 0; r < 4; r++) pa[r] = *(const float4*)(Ap + (size_t)(32 * r) * K);
#pragma unroll
    for (int r = 0; r < 2; r++) pw[r] = *(const float4*)(Wp + (size_t)(32 * r) * K);
#pragma unroll
    for (int r = 0; r < 4; r++) {
        As[0][lkq + 0][lrow + 32 * r] = pa[r].x;
        As[0][lkq + 1][lrow + 32 * r] = pa[r].y;
        As[0][lkq + 2][lrow + 32 * r] = pa[r].z;
        As[0][lkq + 3][lrow + 32 * r] = pa[r].w;
    }
#pragma unroll
    for (int r = 0; r < 2; r++) {
        Ws[0][lkq + 0][lrow + 32 * r] = pw[r].x;
        Ws[0][lkq + 1][lrow + 32 * r] = pw[r].y;
        Ws[0][lkq + 2][lrow + 32 * r] = pw[r].z;
        Ws[0][lkq + 3][lrow + 32 * r] = pw[r].w;
    }
    __syncthreads();

    const int nt = K / BK;
    for (int t = 0; t < nt; t++) {
        const int cur = t & 1;
        const bool more = (t + 1 < nt);

        // prefetch next tile's globals while computing this one
        if (more) {
            const float* Ap2 = Ap + (t + 1) * BK;
            const float* Wp2 = Wp + (t + 1) * BK;
#pragma unroll
            for (int r = 0; r < 4; r++) pa[r] = *(const float4*)(Ap2 + (size_t)(32 * r) * K);
#pragma unroll
            for (int r = 0; r < 2; r++) pw[r] = *(const float4*)(Wp2 + (size_t)(32 * r) * K);
        }

#pragma unroll
        for (int k = 0; k < BK; k++) {
            ulonglong2 av0 = *(const ulonglong2*)&As[cur][k][ty * TM];
            ulonglong2 av1 = *(const ulonglong2*)&As[cur][k][ty * TM + 4];
            float4 wv = *(const float4*)&Ws[cur][k][tx * TN];
            unsigned long long wd0 = dup2(wv.x);
            unsigned long long wd1 = dup2(wv.y);
            unsigned long long wd2 = dup2(wv.z);
            unsigned long long wd3 = dup2(wv.w);
            fma2(acc[0][0], av0.x, wd0); fma2(acc[0][1], av0.x, wd1);
            fma2(acc[0][2], av0.x, wd2); fma2(acc[0][3], av0.x, wd3);
            fma2(acc[1][0], av0.y, wd0); fma2(acc[1][1], av0.y, wd1);
            fma2(acc[1][2], av0.y, wd2); fma2(acc[1][3], av0.y, wd3);
            fma2(acc[2][0], av1.x, wd0); fma2(acc[2][1], av1.x, wd1);
            fma2(acc[2][2], av1.x, wd2); fma2(acc[2][3], av1.x, wd3);
            fma2(acc[3][0], av1.y, wd0); fma2(acc[3][1], av1.y, wd1);
            fma2(acc[3][2], av1.y, wd2); fma2(acc[3][3], av1.y, wd3);
        }

        if (more) {
            const int nxt = cur ^ 1;
#pragma unroll
            for (int r = 0; r < 4; r++) {
                As[nxt][lkq + 0][lrow + 32 * r] = pa[r].x;
                As[nxt][lkq + 1][lrow + 32 * r] = pa[r].y;
                As[nxt][lkq + 2][lrow + 32 * r] = pa[r].z;
                As[nxt][lkq + 3][lrow + 32 * r] = pa[r].w;
            }
#pragma unroll
            for (int r = 0; r < 2; r++) {
                Ws[nxt][lkq + 0][lrow + 32 * r] = pw[r].x;
                Ws[nxt][lkq + 1][lrow + 32 * r] = pw[r].y;
                Ws[nxt][lkq + 2][lrow + 32 * r] = pw[r].z;
                Ws[nxt][lkq + 3][lrow + 32 * r] = pw[r].w;
            }
            __syncthreads();
        }
    }

    float b[TN];
#pragma unroll
    for (int j = 0; j < TN; j++) {
        b[j] = bias[n0 + tx * TN + j];
        if (bias2) b[j] += bias2[n0 + tx * TN + j];
    }

#pragma unroll
    for (int i = 0; i < TM / 2; i++) {
        float lo[TN], hi[TN];
#pragma unroll
        for (int j = 0; j < TN; j++) {
            unpack2(acc[i][j], lo[j], hi[j]);
            lo[j] += b[j]; hi[j] += b[j];
            if (RELU) { lo[j] = fmaxf(lo[j], 0.f); hi[j] = fmaxf(hi[j], 0.f); }
        }
        size_t r0 = (size_t)(m0 + ty * TM + 2 * i) * N + n0 + tx * TN;
        size_t r1 = r0 + N;
        *(float4*)&C[r0] = make_float4(lo[0], lo[1], lo[2], lo[3]);
        *(float4*)&C[r1] = make_float4(hi[0], hi[1], hi[2], hi[3]);
    }
}

// ---------------------------------------------------------------------------
// K2: LSTM scan. 128 CTAs (2 batch rows), 256 threads (2 gate rows each),
// k-packed FFMA2. 20/32 weight chunks in registers, 12 in smem.
// ---------------------------------------------------------------------------
__device__ __forceinline__ float sigf(float x) {
    return __fdividef(1.f, 1.f + __expf(-x));
}
__device__ __forceinline__ float tanhf_fast(float x) {
    return __fdividef(2.f, 1.f + __expf(-2.f * x)) - 1.f;
}

#define SC_KCSM 12
#define SC_KCRG (32 - SC_KCSM)     // 20 chunks/gate in regs
#define HS_PAD  (H_ + 4)
#define SCAN_SMEM ((SC_KCSM * G_ * 4 + 2 * HS_PAD + 2 * G_) * 4)

__global__ __launch_bounds__(256, 1) void k_scan2(float* __restrict__ hT_out,
                                                  float* __restrict__ cT_out)
{
    extern __shared__ float smf[];
    float4* W4s = (float4*)smf;                         // [SC_KCSM*512]
    float*  hsm = smf + SC_KCSM * G_ * 4;               // [2][HS_PAD]
    float*  gsm = hsm + 2 * HS_PAD;                     // [2][512]

    const int t  = threadIdx.x;         // 0..255
    const int g0 = t;                   // gate rows owned
    const int g1 = t + 256;
    const int b0 = blockIdx.x * 2;

    for (int idx = t; idx < SC_KCSM * G_; idx += 256) W4s[idx] = g_wt4[idx];
    ulonglong2 wr0[SC_KCRG], wr1[SC_KCRG];
#pragma unroll
    for (int q = 0; q < SC_KCRG; q++) {
        wr0[q] = *(const ulonglong2*)&g_wt4[(SC_KCSM + q) * G_ + g0];
        wr1[q] = *(const ulonglong2*)&g_wt4[(SC_KCSM + q) * G_ + g1];
    }

    if (t < H_) { hsm[t] = 0.f; hsm[HS_PAD + t] = 0.f; }
    const int eb = t >> 7;
    const int ej = t & 127;
    float cst = 0.f;

    const float* xgp = g_xg + (size_t)b0 * G_;
    float x00 = xgp[g0],      x01 = xgp[G_ + g0];
    float x10 = xgp[g1],      x11 = xgp[G_ + g1];
    __syncthreads();

    for (int ts = 0; ts < T_; ts++) {
        int tn = (ts < T_ - 1) ? ts + 1 : ts;
        const float* xgn = g_xg + ((size_t)tn * B_ + b0) * G_;
        float n00 = xgn[g0], n01 = xgn[G_ + g0];
        float n10 = xgn[g1], n11 = xgn[G_ + g1];

        unsigned long long a00 = 0ull, a01 = 0ull, a10 = 0ull, a11 = 0ull;
#pragma unroll
        for (int kc = 0; kc < 32; kc++) {
            ulonglong2 w0 = (kc < SC_KCSM)
                ? *(const ulonglong2*)&W4s[kc * G_ + g0] : wr0[kc - SC_KCSM];
            ulonglong2 w1 = (kc < SC_KCSM)
                ? *(const ulonglong2*)&W4s[kc * G_ + g1] : wr1[kc - SC_KCSM];
            ulonglong2 h0 = *(const ulonglong2*)&hsm[kc * 4];
            ulonglong2 h1 = *(const ulonglong2*)&hsm[HS_PAD + kc * 4];
            fma2(a00, w0.x, h0.x); fma2(a00, w0.y, h0.y);
            fma2(a01, w0.x, h1.x); fma2(a01, w0.y, h1.y);
            fma2(a10, w1.x, h0.x); fma2(a10, w1.y, h0.y);
            fma2(a11, w1.x, h1.x); fma2(a11, w1.y, h1.y);
        }
        gsm[g0]       = hadd2(a00) + x00;
        gsm[G_ + g0]  = hadd2(a01) + x01;
        gsm[g1]       = hadd2(a10) + x10;
        gsm[G_ + g1]  = hadd2(a11) + x11;
        __syncthreads();

        {
            const float* gb = gsm + eb * G_;
            float ig = sigf(gb[ej]);
            float fg = sigf(gb[H_ + ej]);
            float gg = tanhf_fast(gb[2 * H_ + ej]);
            float og = sigf(gb[3 * H_ + ej]);
            cst = fmaf(fg, cst, ig * gg);
            float hv = og * tanhf_fast(cst);
            hsm[eb * HS_PAD + ej] = hv;
            g_hs[(size_t)(ts * B_ + b0 + eb) * H_ + ej] = hv;
        }
        __syncthreads();
        x00 = n00; x01 = n01; x10 = n10; x11 = n11;
    }

    hT_out[(b0 + eb) * H_ + ej] = hsm[eb * HS_PAD + ej];
    cT_out[(b0 + eb) * H_ + ej] = cst;
}

// ---------------------------------------------------------------------------
// Launcher
// ---------------------------------------------------------------------------
extern "C" void kernel_launch(void* const* d_in, const int* in_sizes, int n_in,
                              void* d_out, int out_size)
{
    const float* x    = (const float*)d_in[0];  // [T,B,I]
    const float* W_ih = (const float*)d_in[1];  // [512,64]
    const float* W_hh = (const float*)d_in[2];  // [512,128]
    const float* b_ih = (const float*)d_in[3];  // [512]
    const float* b_hh = (const float*)d_in[4];  // [512]
    const float* W1   = (const float*)d_in[5];  // [512,128]
    const float* b1   = (const float*)d_in[6];  // [512]
    const float* W2   = (const float*)d_in[7];  // [64,512]
    const float* b2   = (const float*)d_in[8];  // [64]

    float* out = (float*)d_out;                      // [T,B,64]
    float* hT  = out + (size_t)TB_ * O_;             // [1,256,128]
    float* cT  = hT + (size_t)B_ * H_;               // [1,256,128]

    float* xg; float* hs;
    cudaGetSymbolAddress((void**)&xg, g_xg);
    cudaGetSymbolAddress((void**)&hs, g_hs);

    static_assert(SCAN_SMEM <= 232448, "scan smem over limit");
    cudaFuncSetAttribute(k_scan2, cudaFuncAttributeMaxDynamicSharedMemorySize,
                         SCAN_SMEM);

    // K0: weight transpose for the scan
    k_twhh<<<(G_ * H_) / 256, 256>>>(W_hh);

    // K1: xg = x @ W_ih^T + (b_ih + b_hh)   [TB,512]
    k_gemm3<false><<<dim3(TB_ / 128, G_ / 64), 256>>>(
        x, W_ih, b_ih, b_hh, xg, TB_, G_, I_);

    // K2: sequential LSTM scan -> g_hs, hT, cT
    k_scan2<<<B_ / 2, 256, SCAN_SMEM>>>(hT, cT);

    // K3: hidden = relu(hs @ W1^T + b1)   [TB,512]  (reuses g_xg)
    k_gemm3<true><<<dim3(TB_ / 128, NH_ / 64), 256>>>(
        hs, W1, b1, nullptr, xg, TB_, NH_, H_);

    // K4: out = hidden @ W2^T + b2   [TB,64]
    k_gemm3<false><<<dim3(TB_ / 128, O_ / 64), 256>>>(
        xg, W2, b2, nullptr, out, TB_, O_, NH_);
}

// round 12
// speedup vs baseline: 1.6619x; 1.3031x over previous
#include <cuda_runtime.h>
#include <cuda_bf16.h>
#include <cstdint>
#include <cstddef>

// Problem constants
#define T_  2048
#define B_  256
#define I_  64
#define H_  128
#define G_  512          // 4*H gate rows
#define NH_ 512
#define O_  64
#define TB_ (T_ * B_)    // 524288

// ---------------------------------------------------------------------------
// f32x2 packed helpers (scan)
// ---------------------------------------------------------------------------
__device__ __forceinline__ void fma2(unsigned long long& d,
                                     unsigned long long a,
                                     unsigned long long b) {
    asm("fma.rn.f32x2 %0, %1, %2, %0;" : "+l"(d) : "l"(a), "l"(b));
}
__device__ __forceinline__ void unpack2(unsigned long long v, float& lo, float& hi) {
    asm("mov.b64 {%0, %1}, %2;" : "=f"(lo), "=f"(hi) : "l"(v));
}
__device__ __forceinline__ float hadd2(unsigned long long v) {
    float lo, hi; unpack2(v, lo, hi); return lo + hi;
}

__device__ __forceinline__ uint32_t smem_u32(const void* p) {
    uint32_t a;
    asm("{ .reg .u64 t; cvta.to.shared.u64 t, %1; cvt.u32.u64 %0, t; }"
        : "=r"(a) : "l"(p));
    return a;
}

// pack 2 floats -> bf16x2 (lo in low half)
__device__ __forceinline__ uint32_t pkbf2(float lo, float hi) {
    __nv_bfloat162 t = __floats2bfloat162_rn(lo, hi);
    return *(uint32_t*)&t;
}

// split float4 into bf16 hi quad + bf16 lo (residual) quad
__device__ __forceinline__ void split4(float4 v, uint2& hi, uint2& lo) {
    float hx = __bfloat162float(__float2bfloat16(v.x));
    float hy = __bfloat162float(__float2bfloat16(v.y));
    float hz = __bfloat162float(__float2bfloat16(v.z));
    float hw = __bfloat162float(__float2bfloat16(v.w));
    hi = make_uint2(pkbf2(hx, hy), pkbf2(hz, hw));
    lo = make_uint2(pkbf2(v.x - hx, v.y - hy), pkbf2(v.z - hz, v.w - hw));
}

// ldmatrix x4 (no trans)
__device__ __forceinline__ void ldx4(uint32_t& r0, uint32_t& r1,
                                     uint32_t& r2, uint32_t& r3, uint32_t addr) {
    asm volatile("ldmatrix.sync.aligned.m8n8.x4.shared.b16 {%0,%1,%2,%3}, [%4];"
        : "=r"(r0), "=r"(r1), "=r"(r2), "=r"(r3) : "r"(addr));
}

// bf16 mma m16n8k16, fp32 accumulate
__device__ __forceinline__ void mma16816(float* d,
                                         uint32_t a0, uint32_t a1,
                                         uint32_t a2, uint32_t a3,
                                         uint32_t b0, uint32_t b1) {
    asm volatile(
        "mma.sync.aligned.m16n8k16.row.col.f32.bf16.bf16.f32 "
        "{%0,%1,%2,%3}, {%4,%5,%6,%7}, {%8,%9}, {%0,%1,%2,%3};"
        : "+f"(d[0]), "+f"(d[1]), "+f"(d[2]), "+f"(d[3])
        : "r"(a0), "r"(a1), "r"(a2), "r"(a3), "r"(b0), "r"(b1));
}

// ---------------------------------------------------------------------------
// Scratch: __device__ globals (allocation-free rule).
// ---------------------------------------------------------------------------
__device__ float  g_xg[(size_t)TB_ * G_];   // gate preacts; reused as MLP hidden
__device__ float  g_hs[(size_t)TB_ * H_];   // all hidden states
__device__ float4 g_wt4[32 * G_];           // W_hh k-chunked

// ---------------------------------------------------------------------------
// K0: transpose W_hh [512,128] -> g_wt4
// ---------------------------------------------------------------------------
__global__ void k_twhh(const float* __restrict__ Whh) {
    int idx = blockIdx.x * 256 + threadIdx.x;
    int g = idx >> 7;
    int k = idx & 127;
    ((float*)g_wt4)[((k >> 2) * G_ + g) * 4 + (k & 3)] = Whh[idx];
}

// ---------------------------------------------------------------------------
// HMMA GEMM: C[m][n] = sum_k A[m*K+k]*W[n*K+k] + bias[n] (+bias2[n]), opt relu.
// bf16 3-term split (ah*wh + al*wh + ah*wl), fp32 accumulate.
// CTA: 128x64 tile, BK=32, 256 threads = 8 warps (4 m x 2 n, 32x32 warp tile).
// smem rows padded to 80B -> ldmatrix conflict-free. Double buffered.
// ---------------------------------------------------------------------------
#define LDB 80                              // bytes per smem row (40 bf16)
#define ASZ (128 * LDB)                     // 10240
#define WSZ (64 * LDB)                      // 5120
#define BUF (2 * ASZ + 2 * WSZ)             // 30720
#define HG_SMEM (2 * BUF)                   // 61440

template <bool RELU>
__global__ __launch_bounds__(256, 2) void k_hgemm(
    const float* __restrict__ A, const float* __restrict__ W,
    const float* __restrict__ bias, const float* __restrict__ bias2,
    float* __restrict__ C, int M, int N, int K)
{
    extern __shared__ char smem[];
    const uint32_t sb = smem_u32(smem);
    // per-buffer offsets
    const uint32_t AHo = 0, ALo = ASZ, WHo = 2 * ASZ, WLo = 2 * ASZ + WSZ;

    const int tid  = threadIdx.x;
    const int wid  = tid >> 5;
    const int lane = tid & 31;
    const int wm   = wid & 3;           // m warp tile (32 rows each)
    const int wn   = wid >> 2;          // n warp tile (32 cols each)
    const int m0   = blockIdx.x * 128;
    const int n0   = blockIdx.y * 64;

    // staging indices: A: 4 quads/thread, W: 2 quads/thread
    const int am = tid >> 3;            // +32 per iter (4 iters -> 128 rows)
    const int akq = (tid & 7) * 4;      // k quad offset (0..28)

    // ldmatrix base offsets (within a buffer)
    const uint32_t a_off = (uint32_t)((wm * 32 + (lane & 7) + ((lane >> 3) & 1) * 8) * LDB
                                      + (lane >> 4) * 16);
    const uint32_t b_off = (uint32_t)((wn * 32 + (lane & 7) + (lane >> 4) * 8) * LDB
                                      + ((lane >> 3) & 1) * 16);

    float acc[2][4][4];
#pragma unroll
    for (int i = 0; i < 2; i++)
#pragma unroll
        for (int j = 0; j < 4; j++)
#pragma unroll
            for (int q = 0; q < 4; q++) acc[i][j][q] = 0.f;

    float4 pa[4], pw[2];

    // ---- prologue: load tile 0 ----
#pragma unroll
    for (int r = 0; r < 4; r++)
        pa[r] = *(const float4*)&A[(size_t)(m0 + am + 32 * r) * K + akq];
#pragma unroll
    for (int r = 0; r < 2; r++)
        pw[r] = *(const float4*)&W[(size_t)(n0 + am + 32 * r - ((am + 32 * r) & ~63)) * K + akq
                                   + (size_t)0];
    // (simpler W index below; recompute properly)
    {
        int wn_row0 = tid >> 3;         // 0..31 for tid<256? need 64 rows over 2 iters
    }
    // NOTE: W rows: idx = tid + 256*r -> row = idx/8 (0..63), kq = (idx&7)*4
#pragma unroll
    for (int r = 0; r < 2; r++) {
        int idx = tid + 256 * r;
        pw[r] = *(const float4*)&W[(size_t)(n0 + (idx >> 3)) * K + (idx & 7) * 4];
    }

    auto stage = [&](int buf, const float4* va, const float4* vw) {
        uint32_t base = sb + buf * BUF;
#pragma unroll
        for (int r = 0; r < 4; r++) {
            uint2 hi, lo;
            split4(va[r], hi, lo);
            uint32_t off = (uint32_t)((am + 32 * r) * LDB + akq * 2);
            *(uint2*)(smem + (base - sb) + AHo + off) = hi;
            *(uint2*)(smem + (base - sb) + ALo + off) = lo;
        }
#pragma unroll
        for (int r = 0; r < 2; r++) {
            int idx = tid + 256 * r;
            uint2 hi, lo;
            split4(vw[r], hi, lo);
            uint32_t off = (uint32_t)((idx >> 3) * LDB + (idx & 7) * 8);
            *(uint2*)(smem + (base - sb) + WHo + off) = hi;
            *(uint2*)(smem + (base - sb) + WLo + off) = lo;
        }
    };

    stage(0, pa, pw);
    __syncthreads();

    const int nt = K / 32;
    for (int t = 0; t < nt; t++) {
        const int cur = t & 1;
        const bool more = (t + 1 < nt);

        if (more) {
            const float* Ap = A + (t + 1) * 32;
            const float* Wp = W + (t + 1) * 32;
#pragma unroll
            for (int r = 0; r < 4; r++)
                pa[r] = *(const float4*)&Ap[(size_t)(m0 + am + 32 * r) * K + akq];
#pragma unroll
            for (int r = 0; r < 2; r++) {
                int idx = tid + 256 * r;
                pw[r] = *(const float4*)&Wp[(size_t)(n0 + (idx >> 3)) * K + (idx & 7) * 4];
            }
        }

        const uint32_t bufb = sb + cur * BUF;
#pragma unroll
        for (int s = 0; s < 2; s++) {
            const uint32_t ks = s * 32;
            // A fragments (hi and lo), 2 m-frags each
            uint32_t ah[2][4], al[2][4];
            ldx4(ah[0][0], ah[0][1], ah[0][2], ah[0][3], bufb + AHo + a_off + ks);
            ldx4(ah[1][0], ah[1][1], ah[1][2], ah[1][3], bufb + AHo + a_off + 16 * LDB + ks);
            ldx4(al[0][0], al[0][1], al[0][2], al[0][3], bufb + ALo + a_off + ks);
            ldx4(al[1][0], al[1][1], al[1][2], al[1][3], bufb + ALo + a_off + 16 * LDB + ks);
            // B fragments: wh/wl, 2 pairs each (4 n8-frags)
            uint32_t wh[2][4], wl[2][4];
            ldx4(wh[0][0], wh[0][1], wh[0][2], wh[0][3], bufb + WHo + b_off + ks);
            ldx4(wh[1][0], wh[1][1], wh[1][2], wh[1][3], bufb + WHo + b_off + 16 * LDB + ks);
            ldx4(wl[0][0], wl[0][1], wl[0][2], wl[0][3], bufb + WLo + b_off + ks);
            ldx4(wl[1][0], wl[1][1], wl[1][2], wl[1][3], bufb + WLo + b_off + 16 * LDB + ks);

#pragma unroll
            for (int mf = 0; mf < 2; mf++)
#pragma unroll
                for (int nf = 0; nf < 4; nf++) {
                    const int p = nf >> 1, q = (nf & 1) * 2;
                    mma16816(acc[mf][nf], ah[mf][0], ah[mf][1], ah[mf][2], ah[mf][3],
                             wh[p][q], wh[p][q + 1]);
                    mma16816(acc[mf][nf], al[mf][0], al[mf][1], al[mf][2], al[mf][3],
                             wh[p][q], wh[p][q + 1]);
                    mma16816(acc[mf][nf], ah[mf][0], ah[mf][1], ah[mf][2], ah[mf][3],
                             wl[p][q], wl[p][q + 1]);
                }
        }

        if (more) {
            stage(cur ^ 1, pa, pw);
            __syncthreads();
        }
    }

    // ---- epilogue: fragment writeback with bias (+bias2) and relu ----
#pragma unroll
    for (int mf = 0; mf < 2; mf++) {
#pragma unroll
        for (int nf = 0; nf < 4; nf++) {
            int col = n0 + wn * 32 + nf * 8 + (lane & 3) * 2;
            float b0v = bias[col], b1v = bias[col + 1];
            if (bias2) { b0v += bias2[col]; b1v += bias2[col + 1]; }
            int row0 = m0 + wm * 32 + mf * 16 + (lane >> 2);
            float2 o0, o1;
            o0.x = acc[mf][nf][0] + b0v; o0.y = acc[mf][nf][1] + b1v;
            o1.x = acc[mf][nf][2] + b0v; o1.y = acc[mf][nf][3] + b1v;
            if (RELU) {
                o0.x = fmaxf(o0.x, 0.f); o0.y = fmaxf(o0.y, 0.f);
                o1.x = fmaxf(o1.x, 0.f); o1.y = fmaxf(o1.y, 0.f);
            }
            *(float2*)&C[(size_t)row0 * N + col] = o0;
            *(float2*)&C[(size_t)(row0 + 8) * N + col] = o1;
        }
    }
}

// ---------------------------------------------------------------------------
// K2: LSTM scan (unchanged, proven). 128 CTAs, 256 threads, FFMA2.
// ---------------------------------------------------------------------------
__device__ __forceinline__ float sigf(float x) {
    return __fdividef(1.f, 1.f + __expf(-x));
}
__device__ __forceinline__ float tanhf_fast(float x) {
    return __fdividef(2.f, 1.f + __expf(-2.f * x)) - 1.f;
}

#define SC_KCSM 12
#define SC_KCRG (32 - SC_KCSM)
#define HS_PAD  (H_ + 4)
#define SCAN_SMEM ((SC_KCSM * G_ * 4 + 2 * HS_PAD + 2 * G_) * 4)

__global__ __launch_bounds__(256, 1) void k_scan2(float* __restrict__ hT_out,
                                                  float* __restrict__ cT_out)
{
    extern __shared__ float smf[];
    float4* W4s = (float4*)smf;
    float*  hsm = smf + SC_KCSM * G_ * 4;
    float*  gsm = hsm + 2 * HS_PAD;

    const int t  = threadIdx.x;
    const int g0 = t;
    const int g1 = t + 256;
    const int b0 = blockIdx.x * 2;

    for (int idx = t; idx < SC_KCSM * G_; idx += 256) W4s[idx] = g_wt4[idx];
    ulonglong2 wr0[SC_KCRG], wr1[SC_KCRG];
#pragma unroll
    for (int q = 0; q < SC_KCRG; q++) {
        wr0[q] = *(const ulonglong2*)&g_wt4[(SC_KCSM + q) * G_ + g0];
        wr1[q] = *(const ulonglong2*)&g_wt4[(SC_KCSM + q) * G_ + g1];
    }

    if (t < H_) { hsm[t] = 0.f; hsm[HS_PAD + t] = 0.f; }
    const int eb = t >> 7;
    const int ej = t & 127;
    float cst = 0.f;

    const float* xgp = g_xg + (size_t)b0 * G_;
    float x00 = xgp[g0],      x01 = xgp[G_ + g0];
    float x10 = xgp[g1],      x11 = xgp[G_ + g1];
    __syncthreads();

    for (int ts = 0; ts < T_; ts++) {
        int tn = (ts < T_ - 1) ? ts + 1 : ts;
        const float* xgn = g_xg + ((size_t)tn * B_ + b0) * G_;
        float n00 = xgn[g0], n01 = xgn[G_ + g0];
        float n10 = xgn[g1], n11 = xgn[G_ + g1];

        unsigned long long a00 = 0ull, a01 = 0ull, a10 = 0ull, a11 = 0ull;
#pragma unroll
        for (int kc = 0; kc < 32; kc++) {
            ulonglong2 w0 = (kc < SC_KCSM)
                ? *(const ulonglong2*)&W4s[kc * G_ + g0] : wr0[kc - SC_KCSM];
            ulonglong2 w1 = (kc < SC_KCSM)
                ? *(const ulonglong2*)&W4s[kc * G_ + g1] : wr1[kc - SC_KCSM];
            ulonglong2 h0 = *(const ulonglong2*)&hsm[kc * 4];
            ulonglong2 h1 = *(const ulonglong2*)&hsm[HS_PAD + kc * 4];
            fma2(a00, w0.x, h0.x); fma2(a00, w0.y, h0.y);
            fma2(a01, w0.x, h1.x); fma2(a01, w0.y, h1.y);
            fma2(a10, w1.x, h0.x); fma2(a10, w1.y, h0.y);
            fma2(a11, w1.x, h1.x); fma2(a11, w1.y, h1.y);
        }
        gsm[g0]       = hadd2(a00) + x00;
        gsm[G_ + g0]  = hadd2(a01) + x01;
        gsm[g1]       = hadd2(a10) + x10;
        gsm[G_ + g1]  = hadd2(a11) + x11;
        __syncthreads();

        {
            const float* gb = gsm + eb * G_;
            float ig = sigf(gb[ej]);
            float fg = sigf(gb[H_ + ej]);
            float gg = tanhf_fast(gb[2 * H_ + ej]);
            float og = sigf(gb[3 * H_ + ej]);
            cst = fmaf(fg, cst, ig * gg);
            float hv = og * tanhf_fast(cst);
            hsm[eb * HS_PAD + ej] = hv;
            g_hs[(size_t)(ts * B_ + b0 + eb) * H_ + ej] = hv;
        }
        __syncthreads();
        x00 = n00; x01 = n01; x10 = n10; x11 = n11;
    }

    hT_out[(b0 + eb) * H_ + ej] = hsm[eb * HS_PAD + ej];
    cT_out[(b0 + eb) * H_ + ej] = cst;
}

// ---------------------------------------------------------------------------
// Launcher
// ---------------------------------------------------------------------------
extern "C" void kernel_launch(void* const* d_in, const int* in_sizes, int n_in,
                              void* d_out, int out_size)
{
    const float* x    = (const float*)d_in[0];  // [T,B,I]
    const float* W_ih = (const float*)d_in[1];  // [512,64]
    const float* W_hh = (const float*)d_in[2];  // [512,128]
    const float* b_ih = (const float*)d_in[3];  // [512]
    const float* b_hh = (const float*)d_in[4];  // [512]
    const float* W1   = (const float*)d_in[5];  // [512,128]
    const float* b1   = (const float*)d_in[6];  // [512]
    const float* W2   = (const float*)d_in[7];  // [64,512]
    const float* b2   = (const float*)d_in[8];  // [64]

    float* out = (float*)d_out;                      // [T,B,64]
    float* hT  = out + (size_t)TB_ * O_;             // [1,256,128]
    float* cT  = hT + (size_t)B_ * H_;               // [1,256,128]

    float* xg; float* hs;
    cudaGetSymbolAddress((void**)&xg, g_xg);
    cudaGetSymbolAddress((void**)&hs, g_hs);

    static_assert(SCAN_SMEM <= 232448, "scan smem over limit");
    cudaFuncSetAttribute(k_scan2, cudaFuncAttributeMaxDynamicSharedMemorySize,
                         SCAN_SMEM);
    cudaFuncSetAttribute(k_hgemm<false>,
                         cudaFuncAttributeMaxDynamicSharedMemorySize, HG_SMEM);
    cudaFuncSetAttribute(k_hgemm<true>,
                         cudaFuncAttributeMaxDynamicSharedMemorySize, HG_SMEM);

    // K0: weight transpose for the scan
    k_twhh<<<(G_ * H_) / 256, 256>>>(W_hh);

    // K1: xg = x @ W_ih^T + (b_ih + b_hh)   [TB,512], K=64
    k_hgemm<false><<<dim3(TB_ / 128, G_ / 64), 256, HG_SMEM>>>(
        x, W_ih, b_ih, b_hh, xg, TB_, G_, I_);

    // K2: sequential LSTM scan -> g_hs, hT, cT
    k_scan2<<<B_ / 2, 256, SCAN_SMEM>>>(hT, cT);

    // K3: hidden = relu(hs @ W1^T + b1)   [TB,512], K=128 (reuses g_xg)
    k_hgemm<true><<<dim3(TB_ / 128, NH_ / 64), 256, HG_SMEM>>>(
        hs, W1, b1, nullptr, xg, TB_, NH_, H_);

    // K4: out = hidden @ W2^T + b2   [TB,64], K=512
    k_hgemm<false><<<dim3(TB_ / 128, O_ / 64), 256, HG_SMEM>>>(
        xg, W2, b2, nullptr, out, TB_, O_, NH_);
}